// round 3
// baseline (speedup 1.0000x reference)
#include <cuda_runtime.h>
#include <math.h>

#define SEQ   1024
#define BATCH 128
#define IND   300
#define HID   256
#define NCLS  5

// Scratch for x_proj: [SEQ, BATCH, HID] fp32 = 134 MB (device global; no allocs allowed)
__device__ float g_xp[(size_t)SEQ * BATCH * HID];

// ---------------------------------------------------------------------------
// Kernel 1: x_proj[m, n] = inputs[m, :] . W_ih[n, :] + b_ih[n] + b_hh[n]
//   m = s*BATCH + b  (inputs is [S,B,D] row-major -> [M,K] with K=300)
//   Classic 128x128x16 tile, 8x8 per-thread micro-tile, fp32.
// ---------------------------------------------------------------------------
__global__ __launch_bounds__(256, 2) void gemm_xproj(
    const float* __restrict__ A,   // [131072, 300]
    const float* __restrict__ W,   // [256, 300]
    const float* __restrict__ bih,
    const float* __restrict__ bhh)
{
    const int K = IND;
    __shared__ float As[16][128];
    __shared__ float Bs[16][128];

    const int bm  = blockIdx.x * 128;
    const int bn  = blockIdx.y * 128;
    const int tid = threadIdx.x;
    const int trow = tid >> 4;        // 0..15
    const int tcol = tid & 15;        // 0..15

    float acc[8][8];
#pragma unroll
    for (int i = 0; i < 8; i++)
#pragma unroll
        for (int j = 0; j < 8; j++) acc[i][j] = 0.f;

    const int l_r = tid >> 1;         // 0..127 (row within tile)
    const int l_c = (tid & 1) * 8;    // 0 or 8 (k offset within tile)

    for (int k0 = 0; k0 < K; k0 += 16) {
#pragma unroll
        for (int i = 0; i < 8; i++) {
            int k = k0 + l_c + i;
            bool ok = (k < K);
            As[l_c + i][l_r] = ok ? A[(size_t)(bm + l_r) * K + k] : 0.f;
            Bs[l_c + i][l_r] = ok ? W[(size_t)(bn + l_r) * K + k] : 0.f;
        }
        __syncthreads();
#pragma unroll
        for (int kk = 0; kk < 16; kk++) {
            float a[8], b[8];
#pragma unroll
            for (int i = 0; i < 8; i++) a[i] = As[kk][trow * 8 + i];
#pragma unroll
            for (int j = 0; j < 8; j++) b[j] = Bs[kk][tcol * 8 + j];
#pragma unroll
            for (int i = 0; i < 8; i++)
#pragma unroll
                for (int j = 0; j < 8; j++) acc[i][j] += a[i] * b[j];
        }
        __syncthreads();
    }

    // Epilogue: add biases, store to g_xp
    float bias[8];
#pragma unroll
    for (int j = 0; j < 8; j++) {
        int n = bn + tcol * 8 + j;
        bias[j] = bih[n] + bhh[n];
    }
#pragma unroll
    for (int i = 0; i < 8; i++) {
        int m = bm + trow * 8 + i;
        float* dst = g_xp + (size_t)m * HID + bn + tcol * 8;
#pragma unroll
        for (int j = 0; j < 8; j++) dst[j] = acc[i][j] + bias[j];
    }
}

// ---------------------------------------------------------------------------
// Kernel 2: per-batch RNN scan. One CTA per batch element, thread j owns
// hidden unit j. W_hh row j split: k=0..95 from smem (float4-packed over k),
// k=96..255 held in 160 registers (step-invariant). h double-buffered in
// smem; one barrier per step. Readout is linear -> only hsum accumulated.
// ---------------------------------------------------------------------------
#define SKV 96          // k-range served from shared memory
#define SK4 (SKV / 4)   // 24 float4 per hidden unit
#define RKV 160         // k-range held in registers

#define SCAN_SMEM_BYTES ((SK4 * 256 * 4 + 2 * HID + HID + 8) * (int)sizeof(float))

__global__ __launch_bounds__(256, 1) void rnn_scan(
    const float* __restrict__ Whh,   // [256,256] row-major
    const float* __restrict__ Wout,  // [5,256]
    const float* __restrict__ bout,  // [5]
    float* __restrict__ out)         // [128,5]
{
    extern __shared__ float sm[];
    float4* s_w4  = reinterpret_cast<float4*>(sm);    // [SK4][256] float4
    float*  s_h   = sm + SK4 * 256 * 4;               // [2][256]
    float*  s_red = s_h + 2 * HID;                    // [256]
    float*  s_z   = s_red + HID;                      // [8]

    const int j = threadIdx.x;   // hidden unit
    const int b = blockIdx.x;    // batch element

    // Load shared W chunk: s_w4[k4][jj] = Whh[jj][4*k4 .. 4*k4+3]
    for (int idx = j; idx < SK4 * 256; idx += 256) {
        int k4 = idx >> 8;
        int jj = idx & 255;
        s_w4[idx] = reinterpret_cast<const float4*>(Whh)[jj * (HID / 4) + k4];
    }

    // Register-resident W chunk: Whh[j][96..255]
    float wreg[RKV];
    {
        const float4* wrow = reinterpret_cast<const float4*>(Whh + (size_t)j * HID + SKV);
#pragma unroll
        for (int r4 = 0; r4 < RKV / 4; r4++) {
            float4 v = wrow[r4];
            wreg[4 * r4 + 0] = v.x; wreg[4 * r4 + 1] = v.y;
            wreg[4 * r4 + 2] = v.z; wreg[4 * r4 + 3] = v.w;
        }
    }

    s_h[j] = 0.f;
    s_h[HID + j] = 0.f;
    float hsum = 0.f;

    const float* xpb = g_xp + (size_t)b * HID + j;
    float xp_cur = xpb[0];
    __syncthreads();

    int buf = 0;
    for (int s = 0; s < SEQ; s++) {
        float xp_next = 0.f;
        if (s + 1 < SEQ) xp_next = xpb[(size_t)(s + 1) * (BATCH * HID)];

        const float4* h4 = reinterpret_cast<const float4*>(s_h + buf * HID);
        float a0 = 0.f, a1 = 0.f, a2 = 0.f, a3 = 0.f;

#pragma unroll
        for (int k4 = 0; k4 < SK4; k4++) {
            float4 w  = s_w4[(k4 << 8) + j];
            float4 hv = h4[k4];
            a0 += w.x * hv.x; a1 += w.y * hv.y;
            a2 += w.z * hv.z; a3 += w.w * hv.w;
        }
#pragma unroll
        for (int r4 = 0; r4 < RKV / 4; r4++) {
            float4 hv = h4[SK4 + r4];
            a0 += wreg[4 * r4 + 0] * hv.x; a1 += wreg[4 * r4 + 1] * hv.y;
            a2 += wreg[4 * r4 + 2] * hv.z; a3 += wreg[4 * r4 + 3] * hv.w;
        }

        float hn = tanhf(xp_cur + ((a0 + a1) + (a2 + a3)));
        hsum += hn;
        s_h[(buf ^ 1) * HID + j] = hn;
        xp_cur = xp_next;
        buf ^= 1;
        __syncthreads();
    }

    // Readout: out_sum[c] = sum_j Wout[c][j] * hsum[j] + SEQ * bout[c]
    s_red[j] = hsum;
    __syncthreads();

    if (j < NCLS * 32) {
        int c = j >> 5, lane = j & 31;
        float p = 0.f;
#pragma unroll
        for (int t = 0; t < HID / 32; t++)
            p += Wout[c * HID + lane + t * 32] * s_red[lane + t * 32];
#pragma unroll
        for (int off = 16; off > 0; off >>= 1)
            p += __shfl_down_sync(0xffffffffu, p, off);
        if (lane == 0) s_z[c] = p + (float)SEQ * bout[c];
    }
    __syncthreads();

    if (j < NCLS) {
        float z0 = s_z[0], z1 = s_z[1], z2 = s_z[2], z3 = s_z[3], z4 = s_z[4];
        float m = fmaxf(fmaxf(fmaxf(z0, z1), fmaxf(z2, z3)), z4);
        float lse = logf(expf(z0 - m) + expf(z1 - m) + expf(z2 - m) +
                         expf(z3 - m) + expf(z4 - m));
        out[b * NCLS + j] = s_z[j] - m - lse;
    }
}

// One-time, idempotent attribute setup. Returns a dummy value so it can be
// latched in a function-local static (evaluated once, before any capture-path
// stream work ever depends on it). The call is also harmless if repeated.
static int setup_attrs_once() {
    cudaFuncSetAttribute((const void*)rnn_scan,
                         cudaFuncAttributeMaxDynamicSharedMemorySize,
                         SCAN_SMEM_BYTES);
    return 0;
}

// ---------------------------------------------------------------------------
extern "C" void kernel_launch(void* const* d_in, const int* in_sizes, int n_in,
                              void* d_out, int out_size) {
    static int _attrs = setup_attrs_once();  // runs once; no device mem, no sync
    (void)_attrs;

    const float* inputs = (const float*)d_in[0];
    const float* W_ih   = (const float*)d_in[1];
    const float* W_hh   = (const float*)d_in[2];
    const float* b_ih   = (const float*)d_in[3];
    const float* b_hh   = (const float*)d_in[4];
    const float* W_out  = (const float*)d_in[5];
    const float* b_out  = (const float*)d_in[6];
    float* out = (float*)d_out;

    dim3 g1(1024, 2), t1(256);
    gemm_xproj<<<g1, t1>>>(inputs, W_ih, b_ih, b_hh);
    rnn_scan<<<BATCH, HID, SCAN_SMEM_BYTES>>>(W_hh, W_out, b_out, out);
}

// round 5
// speedup vs baseline: 1.1133x; 1.1133x over previous
#include <cuda_runtime.h>
#include <math.h>

#define SEQ   1024
#define BATCH 128
#define IND   300
#define HID   256
#define NCLS  5

// Scratch for x_proj: [SEQ, BATCH, HID] fp32 = 134 MB (device global; no allocs allowed)
__device__ float g_xp[(size_t)SEQ * BATCH * HID];

// ---- packed fp32x2 helpers (Blackwell FFMA2 via PTX; bit-level = 2 floats) ----
__device__ __forceinline__ void ffma2(unsigned long long& d,
                                      unsigned long long a,
                                      unsigned long long b) {
    asm("fma.rn.f32x2 %0, %1, %2, %0;" : "+l"(d) : "l"(a), "l"(b));
}
__device__ __forceinline__ unsigned long long pack2(float x, float y) {
    unsigned long long r;
    asm("mov.b64 %0, {%1, %2};" : "=l"(r) : "f"(x), "f"(y));
    return r;
}
__device__ __forceinline__ float2 unpack2(unsigned long long v) {
    float2 r;
    asm("mov.b64 {%0, %1}, %2;" : "=f"(r.x), "=f"(r.y) : "l"(v));
    return r;
}
__device__ __forceinline__ unsigned long long d_as_ll(double v) {
    return __double_as_longlong(v);
}

// ---------------------------------------------------------------------------
// Kernel 1: x_proj[m, n] = inputs[m, :] . W_ih[n, :] + b_ih[n] + b_hh[n]
//   m = s*BATCH + b. 128x128x16 tile, 8x8 micro-tile, packed f32x2 FMAs.
// ---------------------------------------------------------------------------
__global__ __launch_bounds__(256, 2) void gemm_xproj(
    const float* __restrict__ A,   // [131072, 300]
    const float* __restrict__ W,   // [256, 300]
    const float* __restrict__ bih,
    const float* __restrict__ bhh)
{
    const int K = IND;
    __shared__ __align__(16) float As[16][128];
    __shared__ __align__(16) float Bs[16][128];

    const int bm  = blockIdx.x * 128;
    const int bn  = blockIdx.y * 128;
    const int tid = threadIdx.x;
    const int trow = tid >> 4;        // 0..15
    const int tcol = tid & 15;        // 0..15

    // acc2[i][jj] = packed (acc[i][2jj], acc[i][2jj+1]); bit pattern 0 = (0,0)
    unsigned long long acc2[8][4];
#pragma unroll
    for (int i = 0; i < 8; i++)
#pragma unroll
        for (int jj = 0; jj < 4; jj++) acc2[i][jj] = 0ull;

    const int l_r = tid >> 1;         // 0..127 (row within tile)
    const int l_c = (tid & 1) * 8;    // 0 or 8 (k offset within tile)

    for (int k0 = 0; k0 < K; k0 += 16) {
#pragma unroll
        for (int i = 0; i < 8; i++) {
            int k = k0 + l_c + i;
            bool ok = (k < K);
            As[l_c + i][l_r] = ok ? A[(size_t)(bm + l_r) * K + k] : 0.f;
            Bs[l_c + i][l_r] = ok ? W[(size_t)(bn + l_r) * K + k] : 0.f;
        }
        __syncthreads();
#pragma unroll
        for (int kk = 0; kk < 16; kk++) {
            const float4*  As4 = reinterpret_cast<const float4*>(As[kk]);
            const double2* Bs2 = reinterpret_cast<const double2*>(Bs[kk]);
            float4 a01 = As4[trow * 2];
            float4 a23 = As4[trow * 2 + 1];
            float a[8] = {a01.x, a01.y, a01.z, a01.w, a23.x, a23.y, a23.z, a23.w};
            double2 bA = Bs2[tcol * 2];
            double2 bB = Bs2[tcol * 2 + 1];
            unsigned long long b2[4] = {d_as_ll(bA.x), d_as_ll(bA.y),
                                        d_as_ll(bB.x), d_as_ll(bB.y)};
#pragma unroll
            for (int i = 0; i < 8; i++) {
                unsigned long long ad = pack2(a[i], a[i]);
#pragma unroll
                for (int jj = 0; jj < 4; jj++) ffma2(acc2[i][jj], ad, b2[jj]);
            }
        }
        __syncthreads();
    }

    // Epilogue: add biases, store to g_xp
    float bias[8];
#pragma unroll
    for (int j = 0; j < 8; j++) {
        int n = bn + tcol * 8 + j;
        bias[j] = bih[n] + bhh[n];
    }
#pragma unroll
    for (int i = 0; i < 8; i++) {
        int m = bm + trow * 8 + i;
        float* dst = g_xp + (size_t)m * HID + bn + tcol * 8;
#pragma unroll
        for (int jj = 0; jj < 4; jj++) {
            float2 v = unpack2(acc2[i][jj]);
            dst[2 * jj]     = v.x + bias[2 * jj];
            dst[2 * jj + 1] = v.y + bias[2 * jj + 1];
        }
    }
}

// ---------------------------------------------------------------------------
// Kernel 2: per-batch RNN scan. One CTA per batch element, thread j owns
// hidden unit j. W_hh row j split: k=0..63 from smem (float4-packed over k),
// k=64..255 in 96 packed-u64 registers (step-invariant). All FMAs are packed
// f32x2 fed directly by double2 shared loads (zero pack overhead). h double-
// buffered in smem; one barrier per step. Readout linear -> only hsum kept.
// ---------------------------------------------------------------------------
#define SKV 64          // k-range served from shared memory
#define SK4 (SKV / 4)   // 16 float4 (= double2) per hidden unit
#define RKV 192         // k-range held in registers (96 packed u64)

#define SCAN_SMEM_BYTES ((SK4 * 256 * 4 + 2 * HID + HID + 8) * (int)sizeof(float))

__global__ __launch_bounds__(256, 1) void rnn_scan(
    const float* __restrict__ Whh,   // [256,256] row-major
    const float* __restrict__ Wout,  // [5,256]
    const float* __restrict__ bout,  // [5]
    float* __restrict__ out)         // [128,5]
{
    extern __shared__ __align__(16) float sm[];
    double2* s_wd2 = reinterpret_cast<double2*>(sm);  // [SK4][256] double2 (16B each)
    float*   s_h   = sm + SK4 * 256 * 4;              // [2][256]
    float*   s_red = s_h + 2 * HID;                   // [256]
    float*   s_z   = s_red + HID;                     // [8]

    const int j = threadIdx.x;   // hidden unit
    const int b = blockIdx.x;    // batch element

    // Load shared W chunk: s_wd2[k4*256 + jj] = Whh[jj][4*k4 .. 4*k4+3]
    for (int idx = j; idx < SK4 * 256; idx += 256) {
        int k4 = idx >> 8;
        int jj = idx & 255;
        s_wd2[idx] = reinterpret_cast<const double2*>(Whh)[jj * (HID / 4) + k4];
    }

    // Register-resident W chunk: Whh[j][64..255] as 96 packed u64
    unsigned long long wreg[RKV / 2];
    {
        const double2* wrow =
            reinterpret_cast<const double2*>(Whh + (size_t)j * HID + SKV);
#pragma unroll
        for (int r = 0; r < RKV / 4; r++) {
            double2 v = wrow[r];
            wreg[2 * r]     = d_as_ll(v.x);
            wreg[2 * r + 1] = d_as_ll(v.y);
        }
    }

    s_h[j] = 0.f;
    s_h[HID + j] = 0.f;
    float hsum = 0.f;

    const float* xpb = g_xp + (size_t)b * HID + j;
    float xp_cur = xpb[0];
    __syncthreads();

    int buf = 0;
    for (int s = 0; s < SEQ; s++) {
        float xp_next = 0.f;
        if (s + 1 < SEQ) xp_next = xpb[(size_t)(s + 1) * (BATCH * HID)];

        const double2* h2 = reinterpret_cast<const double2*>(s_h + buf * HID);
        unsigned long long a0 = 0ull, a1 = 0ull, a2 = 0ull, a3 = 0ull;

#pragma unroll
        for (int k4 = 0; k4 < SK4; k4++) {
            double2 wv = s_wd2[(k4 << 8) + j];
            double2 hv = h2[k4];                       // broadcast
            ffma2(a0, d_as_ll(wv.x), d_as_ll(hv.x));
            ffma2(a1, d_as_ll(wv.y), d_as_ll(hv.y));
        }
#pragma unroll
        for (int r = 0; r < RKV / 4; r++) {
            double2 hv = h2[SK4 + r];                  // broadcast
            ffma2(a2, wreg[2 * r],     d_as_ll(hv.x));
            ffma2(a3, wreg[2 * r + 1], d_as_ll(hv.y));
        }

        float2 f0 = unpack2(a0), f1 = unpack2(a1);
        float2 f2 = unpack2(a2), f3 = unpack2(a3);
        float dot = ((f0.x + f0.y) + (f1.x + f1.y)) +
                    ((f2.x + f2.y) + (f3.x + f3.y));

        float hn = tanhf(xp_cur + dot);
        hsum += hn;
        s_h[(buf ^ 1) * HID + j] = hn;
        xp_cur = xp_next;
        buf ^= 1;
        __syncthreads();
    }

    // Readout: out_sum[c] = sum_j Wout[c][j] * hsum[j] + SEQ * bout[c]
    s_red[j] = hsum;
    __syncthreads();

    if (j < NCLS * 32) {
        int c = j >> 5, lane = j & 31;
        float p = 0.f;
#pragma unroll
        for (int t = 0; t < HID / 32; t++)
            p += Wout[c * HID + lane + t * 32] * s_red[lane + t * 32];
#pragma unroll
        for (int off = 16; off > 0; off >>= 1)
            p += __shfl_down_sync(0xffffffffu, p, off);
        if (lane == 0) s_z[c] = p + (float)SEQ * bout[c];
    }
    __syncthreads();

    if (j < NCLS) {
        float z0 = s_z[0], z1 = s_z[1], z2 = s_z[2], z3 = s_z[3], z4 = s_z[4];
        float m = fmaxf(fmaxf(fmaxf(z0, z1), fmaxf(z2, z3)), z4);
        float lse = logf(expf(z0 - m) + expf(z1 - m) + expf(z2 - m) +
                         expf(z3 - m) + expf(z4 - m));
        out[b * NCLS + j] = s_z[j] - m - lse;
    }
}

// One-time, idempotent attribute setup (no device memory, no sync).
static int setup_attrs_once() {
    cudaFuncSetAttribute((const void*)rnn_scan,
                         cudaFuncAttributeMaxDynamicSharedMemorySize,
                         SCAN_SMEM_BYTES);
    return 0;
}

// ---------------------------------------------------------------------------
extern "C" void kernel_launch(void* const* d_in, const int* in_sizes, int n_in,
                              void* d_out, int out_size) {
    static int _attrs = setup_attrs_once();
    (void)_attrs;

    const float* inputs = (const float*)d_in[0];
    const float* W_ih   = (const float*)d_in[1];
    const float* W_hh   = (const float*)d_in[2];
    const float* b_ih   = (const float*)d_in[3];
    const float* b_hh   = (const float*)d_in[4];
    const float* W_out  = (const float*)d_in[5];
    const float* b_out  = (const float*)d_in[6];
    float* out = (float*)d_out;

    dim3 g1(1024, 2), t1(256);
    gemm_xproj<<<g1, t1>>>(inputs, W_ih, b_ih, b_hh);
    rnn_scan<<<BATCH, HID, SCAN_SMEM_BYTES>>>(W_hh, W_out, b_out, out);
}

// round 6
// speedup vs baseline: 1.1133x; 1.0000x over previous
#include <cuda_runtime.h>
#include <math.h>

#define SEQ   1024
#define BATCH 128
#define IND   300
#define HID   256
#define NCLS  5

// Scratch for x_proj: [SEQ, BATCH, HID] fp32 = 134 MB (device global; no allocs allowed)
__device__ float g_xp[(size_t)SEQ * BATCH * HID];

// ---- packed fp32x2 helpers (Blackwell FFMA2 via PTX; bit-level = 2 floats) ----
__device__ __forceinline__ void ffma2(unsigned long long& d,
                                      unsigned long long a,
                                      unsigned long long b) {
    asm("fma.rn.f32x2 %0, %1, %2, %0;" : "+l"(d) : "l"(a), "l"(b));
}
__device__ __forceinline__ unsigned long long pack2(float x, float y) {
    unsigned long long r;
    asm("mov.b64 %0, {%1, %2};" : "=l"(r) : "f"(x), "f"(y));
    return r;
}
__device__ __forceinline__ float2 unpack2(unsigned long long v) {
    float2 r;
    asm("mov.b64 {%0, %1}, %2;" : "=f"(r.x), "=f"(r.y) : "l"(v));
    return r;
}
__device__ __forceinline__ unsigned long long d_as_ll(double v) {
    return __double_as_longlong(v);
}

// ---------------------------------------------------------------------------
// Kernel 1: x_proj[m, n] = inputs[m, :] . W_ih[n, :] + b_ih[n] + b_hh[n]
//   m = s*BATCH + b. 128x128x16 tile, 8x8 micro-tile, packed f32x2 FMAs.
// ---------------------------------------------------------------------------
__global__ __launch_bounds__(256, 2) void gemm_xproj(
    const float* __restrict__ A,   // [131072, 300]
    const float* __restrict__ W,   // [256, 300]
    const float* __restrict__ bih,
    const float* __restrict__ bhh)
{
    const int K = IND;
    __shared__ __align__(16) float As[16][128];
    __shared__ __align__(16) float Bs[16][128];

    const int bm  = blockIdx.x * 128;
    const int bn  = blockIdx.y * 128;
    const int tid = threadIdx.x;
    const int trow = tid >> 4;        // 0..15
    const int tcol = tid & 15;        // 0..15

    // acc2[i][jj] = packed (acc[i][2jj], acc[i][2jj+1]); bit pattern 0 = (0,0)
    unsigned long long acc2[8][4];
#pragma unroll
    for (int i = 0; i < 8; i++)
#pragma unroll
        for (int jj = 0; jj < 4; jj++) acc2[i][jj] = 0ull;

    const int l_r = tid >> 1;         // 0..127 (row within tile)
    const int l_c = (tid & 1) * 8;    // 0 or 8 (k offset within tile)

    for (int k0 = 0; k0 < K; k0 += 16) {
#pragma unroll
        for (int i = 0; i < 8; i++) {
            int k = k0 + l_c + i;
            bool ok = (k < K);
            As[l_c + i][l_r] = ok ? A[(size_t)(bm + l_r) * K + k] : 0.f;
            Bs[l_c + i][l_r] = ok ? W[(size_t)(bn + l_r) * K + k] : 0.f;
        }
        __syncthreads();
#pragma unroll
        for (int kk = 0; kk < 16; kk++) {
            const float4*  As4 = reinterpret_cast<const float4*>(As[kk]);
            const double2* Bs2 = reinterpret_cast<const double2*>(Bs[kk]);
            float4 a01 = As4[trow * 2];
            float4 a23 = As4[trow * 2 + 1];
            float a[8] = {a01.x, a01.y, a01.z, a01.w, a23.x, a23.y, a23.z, a23.w};
            double2 bA = Bs2[tcol * 2];
            double2 bB = Bs2[tcol * 2 + 1];
            unsigned long long b2[4] = {d_as_ll(bA.x), d_as_ll(bA.y),
                                        d_as_ll(bB.x), d_as_ll(bB.y)};
#pragma unroll
            for (int i = 0; i < 8; i++) {
                unsigned long long ad = pack2(a[i], a[i]);
#pragma unroll
                for (int jj = 0; jj < 4; jj++) ffma2(acc2[i][jj], ad, b2[jj]);
            }
        }
        __syncthreads();
    }

    // Epilogue: add biases, store to g_xp
    float bias[8];
#pragma unroll
    for (int j = 0; j < 8; j++) {
        int n = bn + tcol * 8 + j;
        bias[j] = bih[n] + bhh[n];
    }
#pragma unroll
    for (int i = 0; i < 8; i++) {
        int m = bm + trow * 8 + i;
        float* dst = g_xp + (size_t)m * HID + bn + tcol * 8;
#pragma unroll
        for (int jj = 0; jj < 4; jj++) {
            float2 v = unpack2(acc2[i][jj]);
            dst[2 * jj]     = v.x + bias[2 * jj];
            dst[2 * jj + 1] = v.y + bias[2 * jj + 1];
        }
    }
}

// ---------------------------------------------------------------------------
// Kernel 2: per-batch RNN scan. One CTA per batch element, thread j owns
// hidden unit j. W_hh row j split: k=0..63 from smem (float4-packed over k),
// k=64..255 in 96 packed-u64 registers (step-invariant). All FMAs are packed
// f32x2 fed directly by double2 shared loads (zero pack overhead). h double-
// buffered in smem; one barrier per step. Readout linear -> only hsum kept.
// ---------------------------------------------------------------------------
#define SKV 64          // k-range served from shared memory
#define SK4 (SKV / 4)   // 16 float4 (= double2) per hidden unit
#define RKV 192         // k-range held in registers (96 packed u64)

#define SCAN_SMEM_BYTES ((SK4 * 256 * 4 + 2 * HID + HID + 8) * (int)sizeof(float))

__global__ __launch_bounds__(256, 1) void rnn_scan(
    const float* __restrict__ Whh,   // [256,256] row-major
    const float* __restrict__ Wout,  // [5,256]
    const float* __restrict__ bout,  // [5]
    float* __restrict__ out)         // [128,5]
{
    extern __shared__ __align__(16) float sm[];
    double2* s_wd2 = reinterpret_cast<double2*>(sm);  // [SK4][256] double2 (16B each)
    float*   s_h   = sm + SK4 * 256 * 4;              // [2][256]
    float*   s_red = s_h + 2 * HID;                   // [256]
    float*   s_z   = s_red + HID;                     // [8]

    const int j = threadIdx.x;   // hidden unit
    const int b = blockIdx.x;    // batch element

    // Load shared W chunk: s_wd2[k4*256 + jj] = Whh[jj][4*k4 .. 4*k4+3]
    for (int idx = j; idx < SK4 * 256; idx += 256) {
        int k4 = idx >> 8;
        int jj = idx & 255;
        s_wd2[idx] = reinterpret_cast<const double2*>(Whh)[jj * (HID / 4) + k4];
    }

    // Register-resident W chunk: Whh[j][64..255] as 96 packed u64
    unsigned long long wreg[RKV / 2];
    {
        const double2* wrow =
            reinterpret_cast<const double2*>(Whh + (size_t)j * HID + SKV);
#pragma unroll
        for (int r = 0; r < RKV / 4; r++) {
            double2 v = wrow[r];
            wreg[2 * r]     = d_as_ll(v.x);
            wreg[2 * r + 1] = d_as_ll(v.y);
        }
    }

    s_h[j] = 0.f;
    s_h[HID + j] = 0.f;
    float hsum = 0.f;

    const float* xpb = g_xp + (size_t)b * HID + j;
    float xp_cur = xpb[0];
    __syncthreads();

    int buf = 0;
    for (int s = 0; s < SEQ; s++) {
        float xp_next = 0.f;
        if (s + 1 < SEQ) xp_next = xpb[(size_t)(s + 1) * (BATCH * HID)];

        const double2* h2 = reinterpret_cast<const double2*>(s_h + buf * HID);
        unsigned long long a0 = 0ull, a1 = 0ull, a2 = 0ull, a3 = 0ull;

#pragma unroll
        for (int k4 = 0; k4 < SK4; k4++) {
            double2 wv = s_wd2[(k4 << 8) + j];
            double2 hv = h2[k4];                       // broadcast
            ffma2(a0, d_as_ll(wv.x), d_as_ll(hv.x));
            ffma2(a1, d_as_ll(wv.y), d_as_ll(hv.y));
        }
#pragma unroll
        for (int r = 0; r < RKV / 4; r++) {
            double2 hv = h2[SK4 + r];                  // broadcast
            ffma2(a2, wreg[2 * r],     d_as_ll(hv.x));
            ffma2(a3, wreg[2 * r + 1], d_as_ll(hv.y));
        }

        float2 f0 = unpack2(a0), f1 = unpack2(a1);
        float2 f2 = unpack2(a2), f3 = unpack2(a3);
        float dot = ((f0.x + f0.y) + (f1.x + f1.y)) +
                    ((f2.x + f2.y) + (f3.x + f3.y));

        float hn = tanhf(xp_cur + dot);
        hsum += hn;
        s_h[(buf ^ 1) * HID + j] = hn;
        xp_cur = xp_next;
        buf ^= 1;
        __syncthreads();
    }

    // Readout: out_sum[c] = sum_j Wout[c][j] * hsum[j] + SEQ * bout[c]
    s_red[j] = hsum;
    __syncthreads();

    if (j < NCLS * 32) {
        int c = j >> 5, lane = j & 31;
        float p = 0.f;
#pragma unroll
        for (int t = 0; t < HID / 32; t++)
            p += Wout[c * HID + lane + t * 32] * s_red[lane + t * 32];
#pragma unroll
        for (int off = 16; off > 0; off >>= 1)
            p += __shfl_down_sync(0xffffffffu, p, off);
        if (lane == 0) s_z[c] = p + (float)SEQ * bout[c];
    }
    __syncthreads();

    if (j < NCLS) {
        float z0 = s_z[0], z1 = s_z[1], z2 = s_z[2], z3 = s_z[3], z4 = s_z[4];
        float m = fmaxf(fmaxf(fmaxf(z0, z1), fmaxf(z2, z3)), z4);
        float lse = logf(expf(z0 - m) + expf(z1 - m) + expf(z2 - m) +
                         expf(z3 - m) + expf(z4 - m));
        out[b * NCLS + j] = s_z[j] - m - lse;
    }
}

// One-time, idempotent attribute setup (no device memory, no sync).
static int setup_attrs_once() {
    cudaFuncSetAttribute((const void*)rnn_scan,
                         cudaFuncAttributeMaxDynamicSharedMemorySize,
                         SCAN_SMEM_BYTES);
    return 0;
}

// ---------------------------------------------------------------------------
extern "C" void kernel_launch(void* const* d_in, const int* in_sizes, int n_in,
                              void* d_out, int out_size) {
    static int _attrs = setup_attrs_once();
    (void)_attrs;

    const float* inputs = (const float*)d_in[0];
    const float* W_ih   = (const float*)d_in[1];
    const float* W_hh   = (const float*)d_in[2];
    const float* b_ih   = (const float*)d_in[3];
    const float* b_hh   = (const float*)d_in[4];
    const float* W_out  = (const float*)d_in[5];
    const float* b_out  = (const float*)d_in[6];
    float* out = (float*)d_out;

    dim3 g1(1024, 2), t1(256);
    gemm_xproj<<<g1, t1>>>(inputs, W_ih, b_ih, b_hh);
    rnn_scan<<<BATCH, HID, SCAN_SMEM_BYTES>>>(W_hh, W_out, b_out, out);
}